// round 3
// baseline (speedup 1.0000x reference)
#include <cuda_runtime.h>
#include <cstdint>

// Locally-connected 2D: out[oy,ox] = sum_{ky,kx} x[oy+ky, ox+kx] * W[oy,ox,ky,kx]
// x: [450,450] f32, W: [436,436,15,15] f32 (171 MB streamed once), out: [436,436].
// Block = 32 consecutive pixels of one output row. W tile (28.8KB, contiguous,
// 16B-aligned) staged via cp.async (coalesced, high MLP); x tile staged to smem.
// 4 threads/pixel over ky-row partitions; conflict-free LDS; no shuffles.

#define IN_H 450
#define IN_W 450
#define KH 15
#define KW 15
#define OH 436
#define OW 436
#define KSIZE (KH * KW)     // 225
#define TPX 32              // pixels per block
#define XCOLS (TPX + KW - 1) // 46
#define THREADS 128

__global__ __launch_bounds__(THREADS)
void lc2d_kernel(const float* __restrict__ x,
                 const float* __restrict__ W,
                 float* __restrict__ out)
{
    __shared__ float Wsm[TPX * KSIZE];   // 28800 B
    __shared__ float Xsm[KH * XCOLS];    // 2760 B
    __shared__ float Red[THREADS];

    const int row = blockIdx.y;
    const int xc0 = blockIdx.x * TPX;
    const int npx = min(TPX, OW - xc0);        // 32, or 20 for the last tile
    const int pix0 = row * OW + xc0;
    const int tid = threadIdx.x;

    // ---- Stage W tile via cp.async (contiguous, 16B aligned: pix0 % 4 == 0) ----
    const float* Wg = W + (size_t)pix0 * KSIZE;
    const int nf4 = (npx * KSIZE) >> 2;        // 1800 (or 1125)
    const uint32_t wsm = (uint32_t)__cvta_generic_to_shared(Wsm);
    for (int i = tid; i < nf4; i += THREADS) {
        asm volatile("cp.async.cg.shared.global [%0], [%1], 16;"
                     :: "r"(wsm + i * 16), "l"(Wg + i * 4));
    }
    asm volatile("cp.async.commit_group;");

    // ---- Stage x tile (overlaps with the async W stream) ----
    for (int i = tid; i < KH * XCOLS; i += THREADS) {
        const int r = i / XCOLS;
        const int c = i - r * XCOLS;
        const int g = xc0 + c;
        if (g < IN_W)
            Xsm[i] = __ldg(x + (row + r) * IN_W + g);
    }

    asm volatile("cp.async.wait_group 0;");
    __syncthreads();

    // ---- Compute: 4 threads per pixel, partitioned over ky rows ----
    const int p = tid & 31;        // pixel within tile (= lane -> conflict-free)
    const int part = tid >> 5;     // ky-row group: {0-3},{4-7},{8-11},{12-14}

    float sum = 0.0f;
    if (p < npx) {
        const float* wrow = Wsm + p * KSIZE;
        const int nr = (part == 3) ? 3 : 4;    // warp-uniform
#pragma unroll
        for (int r = 0; r < 4; r++) {
            if (r < nr) {
                const int ky = part * 4 + r;
#pragma unroll
                for (int kx = 0; kx < KW; kx++) {
                    // banks: (225p + k) % 32 = (p + k) % 32 -> distinct per lane
                    sum = fmaf(wrow[ky * KW + kx],
                               Xsm[ky * XCOLS + p + kx], sum);
                }
            }
        }
    }

    Red[tid] = sum;
    __syncthreads();

    if (tid < npx) {
        out[pix0 + tid] = Red[tid] + Red[tid + 32] + Red[tid + 64] + Red[tid + 96];
    }
}

extern "C" void kernel_launch(void* const* d_in, const int* in_sizes, int n_in,
                              void* d_out, int out_size)
{
    const float* x = (const float*)d_in[0];
    const float* W = (const float*)d_in[1];
    float* out = (float*)d_out;

    dim3 grid((OW + TPX - 1) / TPX, OH);   // 14 x 436
    lc2d_kernel<<<grid, THREADS>>>(x, W, out);
}